// round 17
// baseline (speedup 1.0000x reference)
#include <cuda_runtime.h>
#include <cstdint>

// LIF recurrence: v = alpha*v + beta*c; spike = (v >= 1); v = spike ? 0 : v.
// Sequential over T=2048, parallel over N=32768.
// Output: out[0 : T*N] = spikes, out[T*N : 2*T*N] = voltages (post-reset).
//
// R13 champion (127.8us, DRAM 76.7%, regs 148): float4, BLOCK=64, GRID=128
// (1 CTA/SM), 64-step cp.async ring, 16-step direction batches, __stcs.
// R17 micro-levers on top:
//  (1) spikes bit-packed during compute (4 bits/step -> 2 uint32) and
//      expanded at flush: regs 148 -> ~90, exact arithmetic.
//  (2) CTA-parity flush order (even: S,V; odd: V,S) to mix the two write
//      regions across the chip at any instant.

#define T_STEPS 2048
#define N_NEUR  32768
#define BLOCK   64
#define VEC     4                   // neurons per thread
#define CHUNK   (BLOCK * VEC)       // 256 neurons per CTA (1 KB per stream-row)
#define GRID    (N_NEUR / CHUNK)    // 128 CTAs, 1 per SM
#define STAGES  64                  // smem ring depth (steps) -> 64 KB
#define GRP     16                  // steps per commit group / direction batch
#define NGRP    (STAGES / GRP)      // 4 groups in flight
#define SMEM_BYTES (STAGES * BLOCK * 16)

__device__ __forceinline__ void cp_async16(unsigned saddr, const float4* gptr)
{
    asm volatile("cp.async.cg.shared.global [%0], [%1], 16;"
                 :: "r"(saddr), "l"(gptr));
}
__device__ __forceinline__ void cp_commit()
{
    asm volatile("cp.async.commit_group;");
}
__device__ __forceinline__ void cp_wait_allow()
{
    asm volatile("cp.async.wait_group %0;" :: "n"(NGRP - 1));
}

__global__ void __launch_bounds__(BLOCK, 1)
lif_kernel(const float* __restrict__ cur,
           const float* __restrict__ v0,
           float* __restrict__ out)
{
    extern __shared__ float4 sbuf[];          // [STAGES * BLOCK]

    const int tid  = threadIdx.x;
    const int base = blockIdx.x * CHUNK + tid * VEC;   // this thread's 4 neurons

    // Reference f32 constants: alpha = f32(exp(-1/20)), beta = f32(1 - alpha)
    const float alpha = (float)0.9512294245007140;
    const float beta  = (float)(1.0 - 0.9512294245007140);

    float4 v = *(const float4*)(v0 + base);

    const float4* cp = (const float4*)(cur + base);        // row stride N_NEUR/4 float4
    float4* sp = (float4*)(out + base);                    // spikes
    float4* vp = (float4*)(out + (size_t)T_STEPS * N_NEUR + base);  // voltages

    const bool s_first = ((blockIdx.x & 1) == 0);          // parity flush order

    const unsigned sbase =
        (unsigned)__cvta_generic_to_shared(sbuf) + (unsigned)tid * 16u;

    // ---- Prime: issue all STAGES stages as NGRP commit groups ----
#pragma unroll
    for (int g = 0; g < NGRP; ++g) {
#pragma unroll
        for (int i = 0; i < GRP; ++i) {
            const int s = g * GRP + i;
            cp_async16(sbase + (unsigned)(s * BLOCK) * 16u,
                       cp + (size_t)s * (N_NEUR / VEC));
        }
        cp_commit();
    }
    cp += (size_t)STAGES * (N_NEUR / VEC);

    // ---- Main loop: one 16-step group per iteration ----
    for (int t = 0; t < T_STEPS; t += GRP) {
        cp_wait_allow();                       // oldest group (steps t..t+15) ready

        const int slot = (t / GRP) & (NGRP - 1);

        // Compute all 16 steps; voltages buffered as float4, spikes packed
        // 4 bits per step into 2 uint32 (exact: spike is binary).
        float4   vv[GRP];                      // post-reset voltages
        uint32_t sbits[GRP / 8] = {0u, 0u};
#pragma unroll
        for (int i = 0; i < GRP; ++i) {
            const float4 c = sbuf[(slot * GRP + i) * BLOCK + tid];
            // explicitly unfused to match reference rounding
            v.x = __fadd_rn(__fmul_rn(alpha, v.x), __fmul_rn(beta, c.x));
            v.y = __fadd_rn(__fmul_rn(alpha, v.y), __fmul_rn(beta, c.y));
            v.z = __fadd_rn(__fmul_rn(alpha, v.z), __fmul_rn(beta, c.z));
            v.w = __fadd_rn(__fmul_rn(alpha, v.w), __fmul_rn(beta, c.w));
            const bool fx = (v.x >= 1.0f);
            const bool fy = (v.y >= 1.0f);
            const bool fz = (v.z >= 1.0f);
            const bool fw = (v.w >= 1.0f);
            sbits[i >> 3] |= ((fx ? 1u : 0u) | (fy ? 2u : 0u)
                            | (fz ? 4u : 0u) | (fw ? 8u : 0u)) << ((i & 7) * 4);
            v.x = fx ? 0.0f : v.x;
            v.y = fy ? 0.0f : v.y;
            v.z = fz ? 0.0f : v.z;
            v.w = fw ? 0.0f : v.w;
            vv[i] = v;
        }

        // Refill this slot for steps t+STAGES..t+STAGES+15.
        if (t + STAGES < T_STEPS) {
#pragma unroll
            for (int i = 0; i < GRP; ++i)
                cp_async16(sbase + (unsigned)((slot * GRP + i) * BLOCK) * 16u,
                           cp + (size_t)i * (N_NEUR / VEC));
            cp += (size_t)GRP * (N_NEUR / VEC);
        }
        cp_commit();                           // empty group near the tail is fine

        // Flush stream-by-stream; order alternates by CTA parity so the two
        // output regions receive writes concurrently chip-wide.
        // Evict-first streaming stores (outputs write-once, never re-read).
        if (s_first) {
#pragma unroll
            for (int i = 0; i < GRP; ++i) {
                const uint32_t nib = sbits[i >> 3] >> ((i & 7) * 4);
                float4 s4;
                s4.x = (nib & 1u) ? 1.0f : 0.0f;
                s4.y = (nib & 2u) ? 1.0f : 0.0f;
                s4.z = (nib & 4u) ? 1.0f : 0.0f;
                s4.w = (nib & 8u) ? 1.0f : 0.0f;
                __stcs(sp + (size_t)i * (N_NEUR / VEC), s4);
            }
#pragma unroll
            for (int i = 0; i < GRP; ++i)
                __stcs(vp + (size_t)i * (N_NEUR / VEC), vv[i]);
        } else {
#pragma unroll
            for (int i = 0; i < GRP; ++i)
                __stcs(vp + (size_t)i * (N_NEUR / VEC), vv[i]);
#pragma unroll
            for (int i = 0; i < GRP; ++i) {
                const uint32_t nib = sbits[i >> 3] >> ((i & 7) * 4);
                float4 s4;
                s4.x = (nib & 1u) ? 1.0f : 0.0f;
                s4.y = (nib & 2u) ? 1.0f : 0.0f;
                s4.z = (nib & 4u) ? 1.0f : 0.0f;
                s4.w = (nib & 8u) ? 1.0f : 0.0f;
                __stcs(sp + (size_t)i * (N_NEUR / VEC), s4);
            }
        }
        sp += (size_t)GRP * (N_NEUR / VEC);
        vp += (size_t)GRP * (N_NEUR / VEC);
    }
}

extern "C" void kernel_launch(void* const* d_in, const int* in_sizes, int n_in,
                              void* d_out, int out_size)
{
    const float* currents = (const float*)d_in[0];   // (T, N) float32
    const float* v0       = (const float*)d_in[1];   // (N,)  float32
    float* out            = (float*)d_out;           // 2*T*N float32

    cudaFuncSetAttribute(lif_kernel,
                         cudaFuncAttributeMaxDynamicSharedMemorySize,
                         SMEM_BYTES);
    lif_kernel<<<GRID, BLOCK, SMEM_BYTES>>>(currents, v0, out);
}